// round 16
// baseline (speedup 1.0000x reference)
#include <cuda_runtime.h>
#include <cstdint>

#define HID   1024
#define BATCH 2
#define SKV   4096
#define SQ    512
#define NH    16
#define NHK   4
#define DH    64

// ---------------- scratch (all GEMM-consumed buffers uint4 => 16B aligned) ----------------
__device__ float g_Q [BATCH * SQ * NH * DH];
__device__ uint4 g_inh [8192 * 1024 / 8], g_inl [8192 * 1024 / 8];
__device__ uint4 g_lath[1024 * 1024 / 8], g_latl[1024 * 1024 / 8];
__device__ uint4 g_wqh [1024 * 1024 / 8], g_wql [1024 * 1024 / 8];
__device__ uint4 g_wkh [ 256 * 1024 / 8], g_wkl [ 256 * 1024 / 8];
__device__ uint4 g_wvh [ 256 * 1024 / 8], g_wvl [ 256 * 1024 / 8];
__device__ uint4 g_woh [1024 * 1024 / 8], g_wol [1024 * 1024 / 8];
__device__ uint4 g_Kh[8192 * 256 / 8], g_Kl[8192 * 256 / 8];
__device__ uint4 g_Vh[8192 * 256 / 8], g_Vl[8192 * 256 / 8];
__device__ uint4 g_AOh[1024 * 512 / 4], g_AOl[1024 * 512 / 4];

// ---------------- helpers ----------------
__device__ __forceinline__ uint32_t pack_bf(float x, float y) {
    uint32_t r;
    asm("cvt.rn.bf16x2.f32 %0, %1, %2;" : "=r"(r) : "f"(y), "f"(x));
    return r;
}
__device__ __forceinline__ void bfsplit2(float x, float y, uint32_t& h, uint32_t& l) {
    h = pack_bf(x, y);
    float hx = __uint_as_float(h << 16);
    float hy = __uint_as_float(h & 0xffff0000u);
    l = pack_bf(x - hx, y - hy);
}
__device__ __forceinline__ void mma16(float* d, const uint32_t* a, const uint32_t* b) {
    asm volatile(
        "mma.sync.aligned.m16n8k16.row.col.f32.bf16.bf16.f32 "
        "{%0,%1,%2,%3},{%4,%5,%6,%7},{%8,%9},{%0,%1,%2,%3};"
        : "+f"(d[0]), "+f"(d[1]), "+f"(d[2]), "+f"(d[3])
        : "r"(a[0]), "r"(a[1]), "r"(a[2]), "r"(a[3]), "r"(b[0]), "r"(b[1]));
}
__device__ __forceinline__ uint32_t smem_u32(const void* p) {
    uint32_t a;
    asm("{ .reg .u64 t; cvta.to.shared.u64 t, %1; cvt.u32.u64 %0, t; }" : "=r"(a) : "l"(p));
    return a;
}
__device__ __forceinline__ void ldsm4(uint32_t* r, uint32_t addr) {
    asm volatile("ldmatrix.sync.aligned.m8n8.x4.shared.b16 {%0,%1,%2,%3}, [%4];"
        : "=r"(r[0]), "=r"(r[1]), "=r"(r[2]), "=r"(r[3]) : "r"(addr));
}
__device__ __forceinline__ void ldsm4t(uint32_t* r, uint32_t addr) {
    asm volatile("ldmatrix.sync.aligned.m8n8.x4.trans.shared.b16 {%0,%1,%2,%3}, [%4];"
        : "=r"(r[0]), "=r"(r[1]), "=r"(r[2]), "=r"(r[3]) : "r"(addr));
}

// ======================================================================
// presplit_all: all six operand tensors in ONE launch (R14-proven).
// ======================================================================
__global__ void __launch_bounds__(256) presplit_all(
    const float4* __restrict__ inp, const float4* __restrict__ lat,
    const float4* __restrict__ wq_, const float4* __restrict__ wk_,
    const float4* __restrict__ wv_, const float4* __restrict__ wo_,
    uint4* __restrict__ inh,  uint4* __restrict__ inl,
    uint4* __restrict__ lath, uint4* __restrict__ latl,
    uint4* __restrict__ wqh,  uint4* __restrict__ wql,
    uint4* __restrict__ wkh,  uint4* __restrict__ wkl,
    uint4* __restrict__ wvh,  uint4* __restrict__ wvl,
    uint4* __restrict__ woh,  uint4* __restrict__ wol)
{
    int i = blockIdx.x * blockDim.x + threadIdx.x;
    const float4* src;
    uint4 *h, *l;
    int o = i;
    if (o < 1048576)            { src = inp; h = inh;  l = inl;  }
    else if ((o -= 1048576) < 131072) { src = lat; h = lath; l = latl; }
    else if ((o -=  131072) < 131072) { src = wq_; h = wqh;  l = wql;  }
    else if ((o -=  131072) <  32768) { src = wk_; h = wkh;  l = wkl;  }
    else if ((o -=   32768) <  32768) { src = wv_; h = wvh;  l = wvl;  }
    else      { o -= 32768;       src = wo_; h = woh;  l = wol;  }

    float4 v0 = src[2 * o], v1 = src[2 * o + 1];
    uint4 H, L;
    bfsplit2(v0.x, v0.y, H.x, L.x);
    bfsplit2(v0.z, v0.w, H.y, L.y);
    bfsplit2(v1.x, v1.y, H.z, L.z);
    bfsplit2(v1.z, v1.w, H.w, L.w);
    h[o] = H; l[o] = L;
}

// ======================================================================
// qkv_proj: fused Q/K/V projection (R14-proven, unchanged). 640 blocks.
// ======================================================================
__global__ void __launch_bounds__(256, 2) qkv_proj(
    const uint16_t* __restrict__ lath, const uint16_t* __restrict__ latl,
    const uint16_t* __restrict__ inh,  const uint16_t* __restrict__ inl,
    const uint16_t* __restrict__ wqh,  const uint16_t* __restrict__ wql,
    const uint16_t* __restrict__ wkh,  const uint16_t* __restrict__ wkl,
    const uint16_t* __restrict__ wvh,  const uint16_t* __restrict__ wvl,
    const float* __restrict__ qnw, const float* __restrict__ knw,
    float* __restrict__ Qout,
    uint32_t* __restrict__ Kh, uint32_t* __restrict__ Kl,
    uint32_t* __restrict__ Vh, uint32_t* __restrict__ Vl)
{
    extern __shared__ char smc[];
    const uint32_t sb = smem_u32(smc);
    constexpr int STAGE = 30720;
    constexpr int O_AL = 10240, O_WH = 20480, O_WL = 25600;
    float* red = (float*)(smc + 2 * STAGE);

    const int bid = blockIdx.x;
    const uint16_t *Ah, *Al, *Wh, *Wl;
    const float* nw = nullptr;
    float* Cf = nullptr;
    uint32_t *Ch = nullptr, *Cl = nullptr;
    int m0, n0, N;
    bool norm, splitout;
    float oscale = 1.0f;
    if (bid < 256) {            // K proj
        Ah = inh; Al = inl; Wh = wkh; Wl = wkl; nw = knw;
        norm = true; splitout = true; N = 256;
        n0 = (bid & 3) * 64; m0 = (bid >> 2) * 128;
        Ch = Kh; Cl = Kl;
    } else if (bid < 512) {     // V proj
        const int t = bid - 256;
        Ah = inh; Al = inl; Wh = wvh; Wl = wvl;
        norm = false; splitout = true; N = 256;
        n0 = (t & 3) * 64; m0 = (t >> 2) * 128;
        Ch = Vh; Cl = Vl;
    } else {                    // Q proj (pre-scaled by log2 e)
        const int t = bid - 512;
        Ah = lath; Al = latl; Wh = wqh; Wl = wql; nw = qnw;
        norm = true; splitout = false; N = 1024;
        n0 = (t & 15) * 64; m0 = (t >> 4) * 128;
        Cf = Qout;
        oscale = 1.4426950408889634f;
    }

    const int tid = threadIdx.x, lane = tid & 31, wid = tid >> 5;
    const int wm = wid >> 1, wn = wid & 1;
    const int g = lane >> 2, c = lane & 3;

    float acc[2][4][4];
#pragma unroll
    for (int mt = 0; mt < 2; mt++)
#pragma unroll
        for (int nt = 0; nt < 4; nt++)
#pragma unroll
            for (int i = 0; i < 4; i++) acc[mt][nt][i] = 0.f;

    const int srow = tid >> 2, sch = tid & 3;
    const size_t abase0 = (size_t)(m0 + srow) * HID + sch * 8;
    const size_t abase1 = (size_t)(m0 + srow + 64) * HID + sch * 8;
    const size_t wbase  = (size_t)(n0 + srow) * HID + sch * 8;
    const int ro = srow * 80 + sch * 16;

    uint4 rAh0, rAh1, rAl0, rAl1, rWh, rWl;
    auto LDGS = [&](int kt) {
        rAh0 = *(const uint4*)(Ah + abase0 + kt);
        rAh1 = *(const uint4*)(Ah + abase1 + kt);
        rAl0 = *(const uint4*)(Al + abase0 + kt);
        rAl1 = *(const uint4*)(Al + abase1 + kt);
        rWh  = *(const uint4*)(Wh + wbase + kt);
        rWl  = *(const uint4*)(Wl + wbase + kt);
    };
    auto STSS = [&](int buf) {
        char* d = smc + buf * STAGE;
        *(uint4*)(d + ro)                  = rAh0;
        *(uint4*)(d + 64 * 80 + ro)        = rAh1;
        *(uint4*)(d + O_AL + ro)           = rAl0;
        *(uint4*)(d + O_AL + 64 * 80 + ro) = rAl1;
        *(uint4*)(d + O_WH + ro)           = rWh;
        *(uint4*)(d + O_WL + ro)           = rWl;
    };

    const uint32_t aoff = (uint32_t)((wm * 32 + (lane & 7) + ((lane >> 3) & 1) * 8) * 80
                                     + ((lane >> 4) & 1) * 16);
    const uint32_t boff = (uint32_t)((wn * 32 + (lane & 7) + ((lane >> 4) & 1) * 8) * 80
                                     + ((lane >> 3) & 1) * 16);

    LDGS(0); STSS(0);
    __syncthreads();

    for (int kt = 0; kt < HID; kt += 32) {
        const int buf = (kt >> 5) & 1;
        const bool more = (kt + 32 < HID);
        if (more) LDGS(kt + 32);

        const uint32_t base = sb + buf * STAGE;
#pragma unroll
        for (int s = 0; s < 2; s++) {
            uint32_t ah[2][4], al[2][4], bhr[8], blr[8];
            ldsm4(bhr,     base + O_WH + boff + s * 32);
            ldsm4(bhr + 4, base + O_WH + boff + 16 * 80 + s * 32);
            ldsm4(blr,     base + O_WL + boff + s * 32);
            ldsm4(blr + 4, base + O_WL + boff + 16 * 80 + s * 32);
#pragma unroll
            for (int mt = 0; mt < 2; mt++) {
                ldsm4(ah[mt], base + aoff + mt * 1280 + s * 32);
                ldsm4(al[mt], base + O_AL + aoff + mt * 1280 + s * 32);
            }
#pragma unroll
            for (int mt = 0; mt < 2; mt++)
#pragma unroll
                for (int nt = 0; nt < 4; nt++) {
                    mma16(acc[mt][nt], ah[mt], bhr + 2 * nt);
                    mma16(acc[mt][nt], al[mt], bhr + 2 * nt);
                    mma16(acc[mt][nt], ah[mt], blr + 2 * nt);
                }
        }
        if (more) {
            STSS(1 - buf);
            __syncthreads();
        }
    }

    if (norm) {
        __syncthreads();
        float ss0[2] = {0.f, 0.f}, ss1[2] = {0.f, 0.f};
#pragma unroll
        for (int mt = 0; mt < 2; mt++)
#pragma unroll
            for (int nt = 0; nt < 4; nt++) {
                ss0[mt] += acc[mt][nt][0] * acc[mt][nt][0] + acc[mt][nt][1] * acc[mt][nt][1];
                ss1[mt] += acc[mt][nt][2] * acc[mt][nt][2] + acc[mt][nt][3] * acc[mt][nt][3];
            }
#pragma unroll
        for (int mt = 0; mt < 2; mt++) {
            ss0[mt] += __shfl_xor_sync(0xffffffffu, ss0[mt], 1);
            ss0[mt] += __shfl_xor_sync(0xffffffffu, ss0[mt], 2);
            ss1[mt] += __shfl_xor_sync(0xffffffffu, ss1[mt], 1);
            ss1[mt] += __shfl_xor_sync(0xffffffffu, ss1[mt], 2);
            if (c == 0) {
                red[(wm * 32 + mt * 16 + g) * 2 + wn]     = ss0[mt];
                red[(wm * 32 + mt * 16 + g + 8) * 2 + wn] = ss1[mt];
            }
        }
        __syncthreads();
        float sc0[2], sc1[2];
#pragma unroll
        for (int mt = 0; mt < 2; mt++) {
            int r = (wm * 32 + mt * 16 + g) * 2;
            sc0[mt] = rsqrtf((red[r] + red[r + 1]) * (1.f / 64.f) + 1e-6f);
            r = (wm * 32 + mt * 16 + g + 8) * 2;
            sc1[mt] = rsqrtf((red[r] + red[r + 1]) * (1.f / 64.f) + 1e-6f);
        }
        float w0[4], w1[4];
#pragma unroll
        for (int nt = 0; nt < 4; nt++) {
            w0[nt] = nw[wn * 32 + nt * 8 + 2 * c];
            w1[nt] = nw[wn * 32 + nt * 8 + 2 * c + 1];
        }
#pragma unroll
        for (int mt = 0; mt < 2; mt++)
#pragma unroll
            for (int nt = 0; nt < 4; nt++) {
                acc[mt][nt][0] *= sc0[mt] * w0[nt];
                acc[mt][nt][1] *= sc0[mt] * w1[nt];
                acc[mt][nt][2] *= sc1[mt] * w0[nt];
                acc[mt][nt][3] *= sc1[mt] * w1[nt];
            }
    }

#pragma unroll
    for (int mt = 0; mt < 2; mt++)
#pragma unroll
        for (int nt = 0; nt < 4; nt++) {
            const int r = m0 + wm * 32 + mt * 16 + g;
            const int col = n0 + wn * 32 + nt * 8 + 2 * c;
            if (splitout) {
                uint32_t h0, l0, h1, l1;
                bfsplit2(acc[mt][nt][0], acc[mt][nt][1], h0, l0);
                bfsplit2(acc[mt][nt][2], acc[mt][nt][3], h1, l1);
                const int i0 = r * (N >> 1) + (col >> 1);
                const int i1 = (r + 8) * (N >> 1) + (col >> 1);
                Ch[i0] = h0; Cl[i0] = l0;
                Ch[i1] = h1; Cl[i1] = l1;
            } else {
                *(float2*)(Cf + (size_t)r * N + col) =
                    make_float2(acc[mt][nt][0] * oscale, acc[mt][nt][1] * oscale);
                *(float2*)(Cf + (size_t)(r + 8) * N + col) =
                    make_float2(acc[mt][nt][2] * oscale, acc[mt][nt][3] * oscale);
            }
        }
}

// ======================================================================
// oproj_pf: O-projection = proven gemm_bf3 body (BM=128, BN=64, same
// addresses) with distance-2 prefetch via TWO register staging sets and
// 2x-unrolled chunk loop (compile-time parity). Every LDG gets >= 1.5
// chunks before its STS -> no exposed 577-cyc latency at 1 CTA/SM.
// ======================================================================
__global__ void __launch_bounds__(256) oproj_pf(
    const uint16_t* __restrict__ Ah, const uint16_t* __restrict__ Al,
    const uint16_t* __restrict__ Wh, const uint16_t* __restrict__ Wl,
    float* __restrict__ C, int M, int N, int Kdim)
{
    extern __shared__ char smc[];
    const uint32_t sb = smem_u32(smc);
    constexpr int STAGE = 30720;
    constexpr int O_AL = 10240, O_WH = 20480, O_WL = 25600;
    constexpr int NCH = 32;           // K=1024 / 32

    const int tid = threadIdx.x, lane = tid & 31, wid = tid >> 5;
    const int wm = wid >> 1, wn = wid & 1;
    const int g = lane >> 2, c = lane & 3;
    const int m0 = blockIdx.y * 128, n0 = blockIdx.x * 64;

    float acc[2][4][4];
#pragma unroll
    for (int mt = 0; mt < 2; mt++)
#pragma unroll
        for (int nt = 0; nt < 4; nt++)
#pragma unroll
            for (int i = 0; i < 4; i++) acc[mt][nt][i] = 0.f;

    const int srow = tid >> 2, sch = tid & 3;
    const size_t abase0 = (size_t)(m0 + srow) * Kdim + sch * 8;
    const size_t abase1 = (size_t)(m0 + srow + 64) * Kdim + sch * 8;
    const size_t wbase  = (size_t)(n0 + srow) * Kdim + sch * 8;
    const int ro = srow * 80 + sch * 16;

    // two staging register sets
    uint4 a0h0, a0h1, a0l0, a0l1, w0h, w0l;   // set 0 -> buf 0
    uint4 a1h0, a1h1, a1l0, a1l1, w1h, w1l;   // set 1 -> buf 1

    auto LDG0 = [&](int ch) {
        const int kt = ch * 32;
        a0h0 = *(const uint4*)(Ah + abase0 + kt);
        a0h1 = *(const uint4*)(Ah + abase1 + kt);
        a0l0 = *(const uint4*)(Al + abase0 + kt);
        a0l1 = *(const uint4*)(Al + abase1 + kt);
        w0h  = *(const uint4*)(Wh + wbase + kt);
        w0l  = *(const uint4*)(Wl + wbase + kt);
    };
    auto LDG1 = [&](int ch) {
        const int kt = ch * 32;
        a1h0 = *(const uint4*)(Ah + abase0 + kt);
        a1h1 = *(const uint4*)(Ah + abase1 + kt);
        a1l0 = *(const uint4*)(Al + abase0 + kt);
        a1l1 = *(const uint4*)(Al + abase1 + kt);
        w1h  = *(const uint4*)(Wh + wbase + kt);
        w1l  = *(const uint4*)(Wl + wbase + kt);
    };
    auto STS0 = [&]() {
        char* d = smc;
        *(uint4*)(d + ro)                  = a0h0;
        *(uint4*)(d + 64 * 80 + ro)        = a0h1;
        *(uint4*)(d + O_AL + ro)           = a0l0;
        *(uint4*)(d + O_AL + 64 * 80 + ro) = a0l1;
        *(uint4*)(d + O_WH + ro)           = w0h;
        *(uint4*)(d + O_WL + ro)           = w0l;
    };
    auto STS1 = [&]() {
        char* d = smc + STAGE;
        *(uint4*)(d + ro)                  = a1h0;
        *(uint4*)(d + 64 * 80 + ro)        = a1h1;
        *(uint4*)(d + O_AL + ro)           = a1l0;
        *(uint4*)(d + O_AL + 64 * 80 + ro) = a1l1;
        *(uint4*)(d + O_WH + ro)           = w1h;
        *(uint4*)(d + O_WL + ro)           = w1l;
    };

    const uint32_t aoff = (uint32_t)((wm * 32 + (lane & 7) + ((lane >> 3) & 1) * 8) * 80
                                     + ((lane >> 4) & 1) * 16);
    const uint32_t boff = (uint32_t)((wn * 32 + (lane & 7) + ((lane >> 4) & 1) * 8) * 80
                                     + ((lane >> 3) & 1) * 16);

    auto COMPUTE = [&](uint32_t base) {
#pragma unroll
        for (int s = 0; s < 2; s++) {
            uint32_t ah[2][4], al[2][4], bhr[8], blr[8];
            ldsm4(bhr,     base + O_WH + boff + s * 32);
            ldsm4(bhr + 4, base + O_WH + boff + 16 * 80 + s * 32);
            ldsm4(blr,     base + O_WL + boff + s * 32);
            ldsm4(blr + 4, base + O_WL + boff + 16 * 80 + s * 32);
#pragma unroll
            for (int mt = 0; mt < 2; mt++) {
                ldsm4(ah[mt], base + aoff + mt * 1280 + s * 32);
                ldsm4(al[mt], base + O_AL + aoff + mt * 1280 + s * 32);
            }
#pragma unroll
            for (int mt = 0; mt < 2; mt++)
#pragma unroll
                for (int nt = 0; nt < 4; nt++) {
                    mma16(acc[mt][nt], ah[mt], bhr + 2 * nt);
                    mma16(acc[mt][nt], al[mt], bhr + 2 * nt);
                    mma16(acc[mt][nt], ah[mt], blr + 2 * nt);
                }
        }
    };

    // prologue: chunk 0 staged, chunk 1 in registers (set 1)
    LDG0(0); STS0(); LDG1(1);
    __syncthreads();

    for (int cc = 0; cc < NCH; cc += 2) {
        // --- even chunk cc: compute buf0 ---
        if (cc + 2 < NCH) LDG0(cc + 2);
        COMPUTE(sb);
        STS1();                         // stage chunk cc+1 (regs from >=1 chunk ago)
        __syncthreads();
        // --- odd chunk cc+1: compute buf1 ---
        if (cc + 3 < NCH) LDG1(cc + 3);
        COMPUTE(sb + STAGE);
        if (cc + 2 < NCH) {
            STS0();                     // stage chunk cc+2
            __syncthreads();
        }
    }

#pragma unroll
    for (int mt = 0; mt < 2; mt++)
#pragma unroll
        for (int nt = 0; nt < 4; nt++) {
            const int r = m0 + wm * 32 + mt * 16 + g;
            const int col = n0 + wn * 32 + nt * 8 + 2 * c;
            *(float2*)(C + (size_t)r * N + col) =
                make_float2(acc[mt][nt][0], acc[mt][nt][1]);
            *(float2*)(C + (size_t)(r + 8) * N + col) =
                make_float2(acc[mt][nt][2], acc[mt][nt][3]);
        }
}

// ======================================================================
// Attention (R14-proven body, unchanged).
// ======================================================================
__global__ void __launch_bounds__(256, 1) attn_mma(
    const float* __restrict__ Qg,
    const uint16_t* __restrict__ Khg, const uint16_t* __restrict__ Klg,
    const uint16_t* __restrict__ Vhg, const uint16_t* __restrict__ Vlg,
    uint32_t* __restrict__ AOh, uint32_t* __restrict__ AOl)
{
    extern __shared__ char smc[];
    constexpr int TILE_B = 9216;
    constexpr int BUF_B  = 4 * TILE_B;
    const uint32_t sbase = smem_u32(smc);

    const int tid = threadIdx.x;
    const int lane = tid & 31, w = tid >> 5;
    const int g = lane >> 2, c = lane & 3;
    const int r8 = lane & 7, mm = lane >> 3;
    const int b = blockIdx.z, hk = blockIdx.y, q0 = blockIdx.x * 32;
    const int head = hk * 4 + (w >> 1);
    const int qi = (w & 1) * 16;

    uint32_t qh[4][4], ql[4][4];
    {
        const float* r0 = Qg + (size_t)(b * SQ + q0 + qi + g) * HID + head * DH;
        const float* r1 = r0 + 8 * (size_t)HID;
#pragma unroll
        for (int s = 0; s < 4; s++) {
            const int cs = 16 * s + 2 * c;
            bfsplit2(r0[cs],     r0[cs + 1], qh[s][0], ql[s][0]);
            bfsplit2(r1[cs],     r1[cs + 1], qh[s][1], ql[s][1]);
            bfsplit2(r0[cs + 8], r0[cs + 9], qh[s][2], ql[s][2]);
            bfsplit2(r1[cs + 8], r1[cs + 9], qh[s][3], ql[s][3]);
        }
    }

    const int crow = tid >> 2;
    const int cch2 = (tid & 3) * 2;
    uint4 rKH[2], rKL[2], rVH[2], rVL[2];
    auto LDGA = [&](int t) {
        const size_t srow = (size_t)(b * SKV + t * 64 + crow) * 256 + hk * 64;
#pragma unroll
        for (int u = 0; u < 2; u++) {
            const size_t soff = srow + (size_t)(cch2 + u) * 8;
            rKH[u] = *(const uint4*)(Khg + soff);
            rKL[u] = *(const uint4*)(Klg + soff);
            rVH[u] = *(const uint4*)(Vhg + soff);
            rVL[u] = *(const uint4*)(Vlg + soff);
        }
    };
    auto STSA = [&](int buf) {
        char* d = smc + buf * BUF_B;
#pragma unroll
        for (int u = 0; u < 2; u++) {
            const int doff = crow * 144 + (cch2 + u) * 16;
            *(uint4*)(d + doff)              = rKH[u];
            *(uint4*)(d + TILE_B + doff)     = rKL[u];
            *(uint4*)(d + 2 * TILE_B + doff) = rVH[u];
            *(uint4*)(d + 3 * TILE_B + doff) = rVL[u];
        }
    };

    float oacc[8][4];
#pragma unroll
    for (int j = 0; j < 8; j++)
#pragma unroll
        for (int i = 0; i < 4; i++) oacc[j][i] = 0.f;
    float lsum0 = 0.f, lsum1 = 0.f;

    const uint32_t k_off = (uint32_t)r8 * 144u + (uint32_t)mm * 16u;
    const uint32_t v_off = ((uint32_t)(8 * (mm & 1) + r8)) * 144u + (uint32_t)(mm >> 1) * 16u;

    LDGA(0); STSA(0);
    __syncthreads();

    for (int t = 0; t < SKV / 64; t++) {
        const int cur = t & 1;
        if (t < SKV / 64 - 1) LDGA(t + 1);

        const uint32_t kh_b = sbase + (uint32_t)cur * BUF_B;
        const uint32_t kl_b = kh_b + TILE_B;
        const uint32_t vh_b = kh_b + 2 * TILE_B;
        const uint32_t vl_b = kh_b + 3 * TILE_B;

        float sacc[8][4];
#pragma unroll
        for (int j = 0; j < 8; j++) {
            const uint32_t ro = (uint32_t)(8 * j) * 144u;
            uint32_t kh[8], kl[8];
            ldsm4(kh,     kh_b + ro + k_off);
            ldsm4(kh + 4, kh_b + ro + k_off + 64u);
            ldsm4(kl,     kl_b + ro + k_off);
            ldsm4(kl + 4, kl_b + ro + k_off + 64u);
#pragma unroll
            for (int i = 0; i < 4; i++) sacc[j][i] = 0.f;
#pragma unroll
            for (int s = 0; s < 4; s++) {
                mma16(sacc[j], qh[s], kh + 2 * s);
                mma16(sacc[j], ql[s], kh + 2 * s);
                mma16(sacc[j], qh[s], kl + 2 * s);
            }
        }

        uint32_t pah[4][4], pal[4][4];
        float rs0 = 0.f, rs1 = 0.f;
#pragma unroll
        for (int j = 0; j < 8; j++) {
            float p0 = exp2f(sacc[j][0]);
            float p1 = exp2f(sacc[j][1]);
            float p2 = exp2f(sacc[j][2]);
            float p3 = exp2f(sacc[j][3]);
            rs0 += p0 + p1;
            rs1 += p2 + p3;
            const int s = j >> 1, o = (j & 1) * 2;
            bfsplit2(p0, p1, pah[s][o],     pal[s][o]);
            bfsplit2(p2, p3, pah[s][o + 1], pal[s][o + 1]);
        }
        rs0 += __shfl_xor_sync(0xffffffffu, rs0, 1);
        rs0 += __shfl_xor_sync(0xffffffffu, rs0, 2);
        rs1 += __shfl_xor_sync(0xffffffffu, rs1, 1);
        rs1 += __shfl_xor_sync(0xffffffffu, rs1, 2);
        lsum0 += rs0;
        lsum1 += rs1;

#pragma unroll
        for (int s = 0; s < 4; s++) {
            const uint32_t so = (uint32_t)(16 * s) * 144u;
#pragma unroll
            for (int jj = 0; jj < 4; jj++) {
                const uint32_t co = so + (uint32_t)(32 * jj) + v_off;
                uint32_t vh[4], vl[4];
                ldsm4t(vh, vh_b + co);
                ldsm4t(vl, vl_b + co);
                mma16(oacc[2 * jj],     pah[s], vh);
                mma16(oacc[2 * jj],     pal[s], vh);
                mma16(oacc[2 * jj],     pah[s], vl);
                mma16(oacc[2 * jj + 1], pah[s], vh + 2);
                mma16(oacc[2 * jj + 1], pal[s], vh + 2);
                mma16(oacc[2 * jj + 1], pah[s], vl + 2);
            }
        }

        if (t < SKV / 64 - 1) {
            STSA(1 - cur);
            __syncthreads();
        }
    }

    const float i0 = 1.f / lsum0, i1 = 1.f / lsum1;
    const int row0 = b * SQ + q0 + qi + g;
    const int colw = head * 32 + c;
#pragma unroll
    for (int j = 0; j < 8; j++) {
        uint32_t h0, l0, h1, l1;
        bfsplit2(oacc[j][0] * i0, oacc[j][1] * i0, h0, l0);
        bfsplit2(oacc[j][2] * i1, oacc[j][3] * i1, h1, l1);
        const int idx0 = row0 * 512 + colw + j * 4;
        const int idx1 = idx0 + 8 * 512;
        AOh[idx0] = h0; AOl[idx0] = l0;
        AOh[idx1] = h1; AOl[idx1] = l1;
    }
}

// ======================================================================
extern "C" void kernel_launch(void* const* d_in, const int* in_sizes, int n_in,
                              void* d_out, int out_size)
{
    (void)in_sizes; (void)n_in; (void)out_size;
    const float* inputs = (const float*)d_in[0];
    const float* latent = (const float*)d_in[1];
    const float* wq     = (const float*)d_in[2];
    const float* wk     = (const float*)d_in[3];
    const float* wv     = (const float*)d_in[4];
    const float* wo     = (const float*)d_in[5];
    const float* qnw    = (const float*)d_in[6];
    const float* knw    = (const float*)d_in[7];
    float* out = (float*)d_out;

    float* Qb;
    cudaGetSymbolAddress((void**)&Qb, g_Q);
    uint4 *inh, *inl, *lath, *latl, *wqh, *wql, *wkh, *wkl, *wvh, *wvl, *woh, *wol;
    cudaGetSymbolAddress((void**)&inh,  g_inh);  cudaGetSymbolAddress((void**)&inl,  g_inl);
    cudaGetSymbolAddress((void**)&lath, g_lath); cudaGetSymbolAddress((void**)&latl, g_latl);
    cudaGetSymbolAddress((void**)&wqh,  g_wqh);  cudaGetSymbolAddress((void**)&wql,  g_wql);
    cudaGetSymbolAddress((void**)&wkh,  g_wkh);  cudaGetSymbolAddress((void**)&wkl,  g_wkl);
    cudaGetSymbolAddress((void**)&wvh,  g_wvh);  cudaGetSymbolAddress((void**)&wvl,  g_wvl);
    cudaGetSymbolAddress((void**)&woh,  g_woh);  cudaGetSymbolAddress((void**)&wol,  g_wol);
    uint4 *kh4, *kl4, *vh4, *vl4, *aoh4, *aol4;
    cudaGetSymbolAddress((void**)&kh4, g_Kh);    cudaGetSymbolAddress((void**)&kl4, g_Kl);
    cudaGetSymbolAddress((void**)&vh4, g_Vh);    cudaGetSymbolAddress((void**)&vl4, g_Vl);
    cudaGetSymbolAddress((void**)&aoh4, g_AOh);  cudaGetSymbolAddress((void**)&aol4, g_AOl);

    const int SMG = 2 * 30720 + 1024;   // 62464
    const int SMO = 2 * 30720;          // 61440
    const int SMA = 2 * 4 * 9216;       // 73728
    cudaFuncSetAttribute(qkv_proj, cudaFuncAttributeMaxDynamicSharedMemorySize, SMG);
    cudaFuncSetAttribute(oproj_pf, cudaFuncAttributeMaxDynamicSharedMemorySize, SMO);
    cudaFuncSetAttribute(attn_mma, cudaFuncAttributeMaxDynamicSharedMemorySize, SMA);

    dim3 blk(256);
    // one fused presplit: 1507328 n8-items = 5888 * 256
    presplit_all<<<5888, blk>>>(
        (const float4*)inputs, (const float4*)latent, (const float4*)wq,
        (const float4*)wk, (const float4*)wv, (const float4*)wo,
        inh, inl, lath, latl, wqh, wql, wkh, wkl, wvh, wvl, woh, wol);
    // fused Q/K/V projections (640 CTAs)
    qkv_proj<<<640, blk, SMG>>>(
        (const uint16_t*)lath, (const uint16_t*)latl,
        (const uint16_t*)inh,  (const uint16_t*)inl,
        (const uint16_t*)wqh,  (const uint16_t*)wql,
        (const uint16_t*)wkh,  (const uint16_t*)wkl,
        (const uint16_t*)wvh,  (const uint16_t*)wvl,
        qnw, knw, Qb,
        (uint32_t*)kh4, (uint32_t*)kl4, (uint32_t*)vh4, (uint32_t*)vl4);
    // attention -> bf16 hi/lo AO
    attn_mma<<<dim3(SQ / 32, NHK, BATCH), blk, SMA>>>(
        Qb, (const uint16_t*)kh4, (const uint16_t*)kl4,
        (const uint16_t*)vh4, (const uint16_t*)vl4,
        (uint32_t*)aoh4, (uint32_t*)aol4);
    // out = AO @ wo^T -> f32 (distance-2 prefetch GEMM)
    oproj_pf<<<dim3(16, 8), blk, SMO>>>(
        (const uint16_t*)aoh4, (const uint16_t*)aol4,
        (const uint16_t*)woh, (const uint16_t*)wol,
        out, BATCH * SQ, HID, HID);
}